// round 15
// baseline (speedup 1.0000x reference)
#include <cuda_runtime.h>
#include <cstdint>

// QConv2d fused, register-resident merged transforms + f32x2 packing.
//   new_rho[(c,P),(c',P')] = sum_{e,e'} cc[c,e] cc[c',e'] A[(e,P),(e',P')]
//   cc[c,e]=uc[c,e+2],  A = (I2 (x) ux (x) uy) rho (same)^T.
// Phase 1: thread = (e, col): 64-row vector GMEM->regs, kron(ux,uy), ->smem.
// Phase 2: thread = (e', row): 64-col vector smem->regs, kron(ux,uy), ->smem.
// f32x2: uy stage packs row-pairs (i=2a,2a+1) -> 256 FMA2 instead of 512 FMA
// (pack/unpack are register-pair MOVs). ux stage scalar (contraction crosses
// the pack dim). Epilogue fully packed (adjacent cols share coefficients).

#define ST 132   // row stride (floats): f4 phases conflict-free (33 odd)
#define NT 256

typedef unsigned long long u64;

__device__ __forceinline__ u64 pk2(float a, float b) {
    u64 r; asm("mov.b64 %0,{%1,%2};" : "=l"(r) : "f"(a), "f"(b)); return r;
}
__device__ __forceinline__ void unpk2(float& lo, float& hi, u64 p) {
    asm("mov.b64 {%0,%1},%2;" : "=f"(lo), "=f"(hi) : "l"(p));
}
__device__ __forceinline__ u64 mul2(u64 a, u64 b) {
    u64 r; asm("mul.rn.f32x2 %0,%1,%2;" : "=l"(r) : "l"(a), "l"(b)); return r;
}
__device__ __forceinline__ void fma2(u64& d, u64 a, u64 b) {
    asm("fma.rn.f32x2 %0,%1,%2,%0;" : "+l"(d) : "l"(a), "l"(b));
}

extern __shared__ float smf[];

__global__ __launch_bounds__(NT, 2)
void qconv2d_kernel(const float* __restrict__ rho,
                    const float* __restrict__ ux,
                    const float* __restrict__ uy,
                    const float* __restrict__ uc,
                    float* __restrict__ out) {
    float* A    = smf;                      // 128 x 132 floats
    u64*   suyd = (u64*)(smf + 128 * ST);   // 64: (uy[k,j], uy[k,j])
    float* sux  = (float*)(suyd + 64);      // 64
    u64*   sccd = (u64*)(sux + 64);         // 8: dup (uc[c,e+2])

    const int t = threadIdx.x;
    const int b = blockIdx.x;

    if (t < 64) { float vy = uy[t]; suyd[t] = pk2(vy, vy); sux[t] = ux[t]; }
    else if (t < 72) {
        int m = t - 64; float v = uc[(m >> 1) * 4 + 2 + (m & 1)];
        sccd[m] = pk2(v, v);
    }
    __syncthreads();

    // ================= Phase 1: row transform (merged uy,ux) =================
    {
        const int col = t & 127, e = t >> 7;
        const float* rb = rho + (size_t)b * 16384 + (size_t)(e * 64) * 128 + col;
        u64 vp[32];                          // vp[a*8+j] = (v[i=2a], v[i=2a+1]) at j
#pragma unroll
        for (int a = 0; a < 4; a++)
#pragma unroll
            for (int j = 0; j < 8; j++)
                vp[a * 8 + j] = pk2(rb[(size_t)(a * 16 + j) * 128],
                                    rb[(size_t)(a * 16 + 8 + j) * 128]);
        // uy stage (packed), in place per pair-octet
#pragma unroll
        for (int a = 0; a < 4; a++) {
            u64 w8[8];
#pragma unroll
            for (int k = 0; k < 8; k++) {
                u64 acc = mul2(suyd[k * 8], vp[a * 8]);
#pragma unroll
                for (int j = 1; j < 8; j++) fma2(acc, suyd[k * 8 + j], vp[a * 8 + j]);
                w8[k] = acc;
            }
#pragma unroll
            for (int k = 0; k < 8; k++) vp[a * 8 + k] = w8[k];
        }
        // unpack to scalars: w[i*8+k], i=2a -> lo, i=2a+1 -> hi
        float w[64];
#pragma unroll
        for (int a = 0; a < 4; a++)
#pragma unroll
            for (int k = 0; k < 8; k++)
                unpk2(w[a * 16 + k], w[a * 16 + 8 + k], vp[a * 8 + k]);
        // ux stage scalar, one ki octet at a time -> STS immediately
#pragma unroll
        for (int ki = 0; ki < 8; ki++) {
            float acc[8];
            const float c0 = sux[ki * 8];
#pragma unroll
            for (int kj = 0; kj < 8; kj++) acc[kj] = c0 * w[kj];
#pragma unroll
            for (int i = 1; i < 8; i++) {
                const float cf = sux[ki * 8 + i];
#pragma unroll
                for (int kj = 0; kj < 8; kj++) acc[kj] = fmaf(cf, w[i * 8 + kj], acc[kj]);
            }
#pragma unroll
            for (int kj = 0; kj < 8; kj++)
                A[(e * 64 + ki * 8 + kj) * ST + col] = acc[kj];    // conflict-free STS
        }
    }
    __syncthreads();

    // ================= Phase 2: column transform (merged uy,ux) =================
    {
        const int r = t & 127, e2 = t >> 7;
        const int base = r * ST + e2 * 64;
        float4 f[16];
#pragma unroll
        for (int m = 0; m < 16; m++) f[m] = *(float4*)&A[base + 4 * m];  // LDS.128
        u64 vp[32];
#pragma unroll
        for (int a = 0; a < 4; a++)
#pragma unroll
            for (int j = 0; j < 8; j++) {
                const float* fv = (const float*)&f[0];
                vp[a * 8 + j] = pk2(fv[a * 16 + j], fv[a * 16 + 8 + j]);
            }
#pragma unroll
        for (int a = 0; a < 4; a++) {
            u64 w8[8];
#pragma unroll
            for (int k = 0; k < 8; k++) {
                u64 acc = mul2(suyd[k * 8], vp[a * 8]);
#pragma unroll
                for (int j = 1; j < 8; j++) fma2(acc, suyd[k * 8 + j], vp[a * 8 + j]);
                w8[k] = acc;
            }
#pragma unroll
            for (int k = 0; k < 8; k++) vp[a * 8 + k] = w8[k];
        }
        float w[64];
#pragma unroll
        for (int a = 0; a < 4; a++)
#pragma unroll
            for (int k = 0; k < 8; k++)
                unpk2(w[a * 16 + k], w[a * 16 + 8 + k], vp[a * 8 + k]);
#pragma unroll
        for (int ki = 0; ki < 8; ki++) {
            float acc[8];
            const float c0 = sux[ki * 8];
#pragma unroll
            for (int kj = 0; kj < 8; kj++) acc[kj] = c0 * w[kj];
#pragma unroll
            for (int i = 1; i < 8; i++) {
                const float cf = sux[ki * 8 + i];
#pragma unroll
                for (int kj = 0; kj < 8; kj++) acc[kj] = fmaf(cf, w[i * 8 + kj], acc[kj]);
            }
            *(float4*)&A[base + ki * 8]     = make_float4(acc[0], acc[1], acc[2], acc[3]);
            *(float4*)&A[base + ki * 8 + 4] = make_float4(acc[4], acc[5], acc[6], acc[7]);
        }
    }
    __syncthreads();

    // ================= Epilogue: read-once channel expansion (packed) =========
    const u64 s0 = sccd[0], s1 = sccd[1], s2 = sccd[2], s3 = sccd[3];
    const u64 s4 = sccd[4], s5 = sccd[5], s6 = sccd[6], s7 = sccd[7];
#pragma unroll 1
    for (int it = 0; it < 4; it++) {
        const int task = t + NT * it;
        const int q = task & 15, P = task >> 4;      // q: col quad 0..15, P: 0..63
        float4 A00 = *(float4*)&A[P * ST + 4 * q];
        float4 A01 = *(float4*)&A[P * ST + 64 + 4 * q];
        float4 A10 = *(float4*)&A[(64 + P) * ST + 4 * q];
        float4 A11 = *(float4*)&A[(64 + P) * ST + 64 + 4 * q];
        u64 a00x = pk2(A00.x, A00.y), a00z = pk2(A00.z, A00.w);
        u64 a01x = pk2(A01.x, A01.y), a01z = pk2(A01.z, A01.w);
        u64 a10x = pk2(A10.x, A10.y), a10z = pk2(A10.z, A10.w);
        u64 a11x = pk2(A11.x, A11.y), a11z = pk2(A11.z, A11.w);
        float* ob = out + (size_t)b * 65536 + (size_t)P * 256 + 4 * q;
#pragma unroll
        for (int cp = 0; cp < 4; cp++) {
            const u64 k0 = sccd[2 * cp], k1 = sccd[2 * cp + 1];
            u64 v0x = mul2(k0, a00x); fma2(v0x, k1, a01x);
            u64 v0z = mul2(k0, a00z); fma2(v0z, k1, a01z);
            u64 v1x = mul2(k0, a10x); fma2(v1x, k1, a11x);
            u64 v1z = mul2(k0, a10z); fma2(v1z, k1, a11z);
            ulonglong2 wv;
            wv.x = mul2(s0, v0x); fma2(wv.x, s1, v1x);
            wv.y = mul2(s0, v0z); fma2(wv.y, s1, v1z);
            *(ulonglong2*)(ob + (size_t)(0 * 64) * 256 + cp * 64) = wv;
            wv.x = mul2(s2, v0x); fma2(wv.x, s3, v1x);
            wv.y = mul2(s2, v0z); fma2(wv.y, s3, v1z);
            *(ulonglong2*)(ob + (size_t)(1 * 64) * 256 + cp * 64) = wv;
            wv.x = mul2(s4, v0x); fma2(wv.x, s5, v1x);
            wv.y = mul2(s4, v0z); fma2(wv.y, s5, v1z);
            *(ulonglong2*)(ob + (size_t)(2 * 64) * 256 + cp * 64) = wv;
            wv.x = mul2(s6, v0x); fma2(wv.x, s7, v1x);
            wv.y = mul2(s6, v0z); fma2(wv.y, s7, v1z);
            *(ulonglong2*)(ob + (size_t)(3 * 64) * 256 + cp * 64) = wv;
        }
    }
}

extern "C" void kernel_launch(void* const* d_in, const int* in_sizes, int n_in,
                              void* d_out, int out_size) {
    const float* rho = (const float*)d_in[0];   // [256,128,128]
    const float* ux  = (const float*)d_in[1];   // [8,8]
    const float* uy  = (const float*)d_in[2];   // [8,8]
    const float* uc  = (const float*)d_in[3];   // [4,4]
    float* out = (float*)d_out;                 // [256,256,256]

    const size_t smem = (128 * ST) * sizeof(float)
                      + 64 * sizeof(u64) + 64 * sizeof(float) + 8 * sizeof(u64);
    cudaFuncSetAttribute(qconv2d_kernel,
                         cudaFuncAttributeMaxDynamicSharedMemorySize, (int)smem);
    qconv2d_kernel<<<256, NT, smem>>>(rho, ux, uy, uc, out);
}

// round 16
// speedup vs baseline: 1.6637x; 1.6637x over previous
#include <cuda_runtime.h>
#include <cstdint>

// QConv2d fused, register-resident merged transforms (R14 scalar phases)
// + f32x2-packed epilogue only (R15's phase packing spilled; reverted).
//   new_rho[(c,P),(c',P')] = sum_{e,e'} cc[c,e] cc[c',e'] A[(e,P),(e',P')]
//   cc[c,e]=uc[c,e+2],  A = (I2 (x) ux (x) uy) rho (same)^T.
// Phase 1: thread = (e, col): 64-row vector GMEM->regs, kron(ux,uy), ->smem.
// Phase 2: thread = (e', row): 64-col vector smem->regs, kron(ux,uy), ->smem.
// Epilogue: read-once channel expansion, f32x2 math, STG.128.

#define ST 132   // row stride (floats): f4 phases conflict-free (33 odd)
#define NT 256

typedef unsigned long long u64;

__device__ __forceinline__ u64 pk2(float a, float b) {
    u64 r; asm("mov.b64 %0,{%1,%2};" : "=l"(r) : "f"(a), "f"(b)); return r;
}
__device__ __forceinline__ u64 mul2(u64 a, u64 b) {
    u64 r; asm("mul.rn.f32x2 %0,%1,%2;" : "=l"(r) : "l"(a), "l"(b)); return r;
}
__device__ __forceinline__ void fma2(u64& d, u64 a, u64 b) {
    asm("fma.rn.f32x2 %0,%1,%2,%0;" : "+l"(d) : "l"(a), "l"(b));
}

extern __shared__ float smf[];

__global__ __launch_bounds__(NT, 2)
void qconv2d_kernel(const float* __restrict__ rho,
                    const float* __restrict__ ux,
                    const float* __restrict__ uy,
                    const float* __restrict__ uc,
                    float* __restrict__ out) {
    float* A    = smf;                      // 128 x 132 floats
    float* sux  = smf + 128 * ST;           // 64
    float* suy  = sux + 64;                 // 64
    u64*   sccd = (u64*)(suy + 64);         // 8: dup (uc[c,e+2])

    const int t = threadIdx.x;
    const int b = blockIdx.x;

    if (t < 64) { sux[t] = ux[t]; suy[t] = uy[t]; }
    else if (t < 72) {
        int m = t - 64; float v = uc[(m >> 1) * 4 + 2 + (m & 1)];
        sccd[m] = pk2(v, v);
    }
    __syncthreads();

    // ================= Phase 1: row transform (merged uy,ux) =================
    {
        const int col = t & 127, e = t >> 7;
        const float* rb = rho + (size_t)b * 16384 + (size_t)(e * 64) * 128 + col;
        float v[64];
#pragma unroll
        for (int m = 0; m < 64; m++) v[m] = rb[(size_t)m * 128];   // coalesced LDG
        // uy stage, in place per octet: v[i*8+k] <- sum_j suy[k,j] v[i*8+j]
#pragma unroll
        for (int i = 0; i < 8; i++) {
            float w[8];
#pragma unroll
            for (int k = 0; k < 8; k++) {
                float acc = suy[k * 8] * v[i * 8];
#pragma unroll
                for (int j = 1; j < 8; j++) acc = fmaf(suy[k * 8 + j], v[i * 8 + j], acc);
                w[k] = acc;
            }
#pragma unroll
            for (int k = 0; k < 8; k++) v[i * 8 + k] = w[k];
        }
        // ux stage, one output octet at a time -> STS immediately
#pragma unroll
        for (int ki = 0; ki < 8; ki++) {
            float acc[8];
            {
                const float cf = sux[ki * 8];
#pragma unroll
                for (int kj = 0; kj < 8; kj++) acc[kj] = cf * v[kj];
            }
#pragma unroll
            for (int i = 1; i < 8; i++) {
                const float cf = sux[ki * 8 + i];
#pragma unroll
                for (int kj = 0; kj < 8; kj++) acc[kj] = fmaf(cf, v[i * 8 + kj], acc[kj]);
            }
#pragma unroll
            for (int kj = 0; kj < 8; kj++)
                A[(e * 64 + ki * 8 + kj) * ST + col] = acc[kj];    // conflict-free STS
        }
    }
    __syncthreads();

    // ================= Phase 2: column transform (merged uy,ux) =================
    {
        const int r = t & 127, e2 = t >> 7;
        const int base = r * ST + e2 * 64;
        float v[64];
#pragma unroll
        for (int m = 0; m < 16; m++)
            *(float4*)&v[4 * m] = *(float4*)&A[base + 4 * m];      // LDS.128 c-free
#pragma unroll
        for (int i = 0; i < 8; i++) {
            float w[8];
#pragma unroll
            for (int k = 0; k < 8; k++) {
                float acc = suy[k * 8] * v[i * 8];
#pragma unroll
                for (int j = 1; j < 8; j++) acc = fmaf(suy[k * 8 + j], v[i * 8 + j], acc);
                w[k] = acc;
            }
#pragma unroll
            for (int k = 0; k < 8; k++) v[i * 8 + k] = w[k];
        }
#pragma unroll
        for (int ki = 0; ki < 8; ki++) {
            float acc[8];
            {
                const float cf = sux[ki * 8];
#pragma unroll
                for (int kj = 0; kj < 8; kj++) acc[kj] = cf * v[kj];
            }
#pragma unroll
            for (int i = 1; i < 8; i++) {
                const float cf = sux[ki * 8 + i];
#pragma unroll
                for (int kj = 0; kj < 8; kj++) acc[kj] = fmaf(cf, v[i * 8 + kj], acc[kj]);
            }
            *(float4*)&A[base + ki * 8]     = make_float4(acc[0], acc[1], acc[2], acc[3]);
            *(float4*)&A[base + ki * 8 + 4] = make_float4(acc[4], acc[5], acc[6], acc[7]);
        }
    }
    __syncthreads();

    // ============ Epilogue: read-once channel expansion (f32x2 packed) ========
    const u64 s0 = sccd[0], s1 = sccd[1], s2 = sccd[2], s3 = sccd[3];
    const u64 s4 = sccd[4], s5 = sccd[5], s6 = sccd[6], s7 = sccd[7];
#pragma unroll 1
    for (int it = 0; it < 4; it++) {
        const int task = t + NT * it;
        const int q = task & 15, P = task >> 4;      // q: col quad 0..15, P: 0..63
        ulonglong2 a00 = *(ulonglong2*)&A[P * ST + 4 * q];
        ulonglong2 a01 = *(ulonglong2*)&A[P * ST + 64 + 4 * q];
        ulonglong2 a10 = *(ulonglong2*)&A[(64 + P) * ST + 4 * q];
        ulonglong2 a11 = *(ulonglong2*)&A[(64 + P) * ST + 64 + 4 * q];
        float* ob = out + (size_t)b * 65536 + (size_t)P * 256 + 4 * q;
#pragma unroll
        for (int cp = 0; cp < 4; cp++) {
            const u64 k0 = sccd[2 * cp], k1 = sccd[2 * cp + 1];
            u64 v0x = mul2(k0, a00.x); fma2(v0x, k1, a01.x);
            u64 v0z = mul2(k0, a00.y); fma2(v0z, k1, a01.y);
            u64 v1x = mul2(k0, a10.x); fma2(v1x, k1, a11.x);
            u64 v1z = mul2(k0, a10.y); fma2(v1z, k1, a11.y);
            ulonglong2 wv;
            wv.x = mul2(s0, v0x); fma2(wv.x, s1, v1x);
            wv.y = mul2(s0, v0z); fma2(wv.y, s1, v1z);
            *(ulonglong2*)(ob + (size_t)(0 * 64) * 256 + cp * 64) = wv;
            wv.x = mul2(s2, v0x); fma2(wv.x, s3, v1x);
            wv.y = mul2(s2, v0z); fma2(wv.y, s3, v1z);
            *(ulonglong2*)(ob + (size_t)(1 * 64) * 256 + cp * 64) = wv;
            wv.x = mul2(s4, v0x); fma2(wv.x, s5, v1x);
            wv.y = mul2(s4, v0z); fma2(wv.y, s5, v1z);
            *(ulonglong2*)(ob + (size_t)(2 * 64) * 256 + cp * 64) = wv;
            wv.x = mul2(s6, v0x); fma2(wv.x, s7, v1x);
            wv.y = mul2(s6, v0z); fma2(wv.y, s7, v1z);
            *(ulonglong2*)(ob + (size_t)(3 * 64) * 256 + cp * 64) = wv;
        }
    }
}

extern "C" void kernel_launch(void* const* d_in, const int* in_sizes, int n_in,
                              void* d_out, int out_size) {
    const float* rho = (const float*)d_in[0];   // [256,128,128]
    const float* ux  = (const float*)d_in[1];   // [8,8]
    const float* uy  = (const float*)d_in[2];   // [8,8]
    const float* uc  = (const float*)d_in[3];   // [4,4]
    float* out = (float*)d_out;                 // [256,256,256]

    const size_t smem = (128 * ST + 64 + 64) * sizeof(float) + 8 * sizeof(u64);
    cudaFuncSetAttribute(qconv2d_kernel,
                         cudaFuncAttributeMaxDynamicSharedMemorySize, (int)smem);
    qconv2d_kernel<<<256, NT, smem>>>(rho, ux, uy, uc, out);
}